// round 8
// baseline (speedup 1.0000x reference)
#include <cuda_runtime.h>

#define BS   8192
#define H    256
#define KC   64
#define RPB  64                 // rows per block in Q kernel
#define NBLK (BS / RPB)         // 128 blocks

typedef unsigned long long ull;

// Packed fp32x2 FMA: d = a*b + d (elementwise on 2 packed floats)
#define FMA2(d, a, b) \
    asm("fma.rn.f32x2 %0, %1, %2, %0;" : "+l"(d) : "l"(a), "l"(b))

// Per-block partial column sums of normalized Q, inverse colsums, arrival counter
__device__ float g_colpart[NBLK * KC];
__device__ float g_csi[KC];
__device__ unsigned int g_cnt = 0;

// ---------------------------------------------------------------------------
// Kernel 1: Q = rownorm( 1/(1+dist) ) + column partials + (last block) colsums.
// Block: 256 threads, tile 64 rows x 64 clusters, per-thread 4x4 register tile.
// Inner loop: 3x LDS.128 + 8x fma.rn.f32x2  (32 lane-FMAs / 11 issue slots).
// smem: zdupT[k][2r] (z duplicated pairs, 128KB) + cT[k][j] (64KB) + extras.
// ---------------------------------------------------------------------------
__global__ __launch_bounds__(256, 1)
void qk_kernel(const float* __restrict__ z, const float* __restrict__ cent,
               float* __restrict__ Qout)
{
    extern __shared__ float smem[];
    float* zdupT  = smem;                        // [256][128] {z,z} pairs
    float* cT     = zdupT + H * 2 * RPB;         // [256][64]
    float* cnp    = cT + H * KC;                 // [4][64] centroid-norm partials
    float* znp    = cnp + 4 * KC;                // [4][64] z-norm partials
    float* cn     = znp + 4 * RPB;               // [64]
    float* zz     = cn + KC;                     // [64]
    float* colred = zz + RPB;                    // [16][64]

    const int tid  = threadIdx.x;
    const int row0 = blockIdx.x * RPB;

    // ---- staging: z (duplicated pairs) + centroids, fused norms ----
    {
        const int rr  = tid & 63;
        const int kg0 = tid >> 6;

        float zsq = 0.f;
        #pragma unroll
        for (int p = 0; p < 16; p++) {
            const int kg = kg0 + p * 4;
            const float4 v = *(const float4*)(z + (size_t)(row0 + rr) * H + kg * 4);
            float* d0 = zdupT + (kg * 4 + 0) * (2 * RPB) + 2 * rr;
            float* d1 = zdupT + (kg * 4 + 1) * (2 * RPB) + 2 * rr;
            float* d2 = zdupT + (kg * 4 + 2) * (2 * RPB) + 2 * rr;
            float* d3 = zdupT + (kg * 4 + 3) * (2 * RPB) + 2 * rr;
            *(float2*)d0 = make_float2(v.x, v.x);
            *(float2*)d1 = make_float2(v.y, v.y);
            *(float2*)d2 = make_float2(v.z, v.z);
            *(float2*)d3 = make_float2(v.w, v.w);
            zsq = fmaf(v.x, v.x, zsq); zsq = fmaf(v.y, v.y, zsq);
            zsq = fmaf(v.z, v.z, zsq); zsq = fmaf(v.w, v.w, zsq);
        }
        znp[kg0 * 64 + rr] = zsq;

        float csq = 0.f;
        #pragma unroll
        for (int p = 0; p < 16; p++) {
            const int kg = kg0 + p * 4;
            const float4 v = *(const float4*)(cent + (size_t)rr * H + kg * 4);
            cT[(kg * 4 + 0) * KC + rr] = v.x;
            cT[(kg * 4 + 1) * KC + rr] = v.y;
            cT[(kg * 4 + 2) * KC + rr] = v.z;
            cT[(kg * 4 + 3) * KC + rr] = v.w;
            csq = fmaf(v.x, v.x, csq); csq = fmaf(v.y, v.y, csq);
            csq = fmaf(v.z, v.z, csq); csq = fmaf(v.w, v.w, csq);
        }
        cnp[kg0 * 64 + rr] = csq;
    }
    __syncthreads();

    if (tid < 64)
        cn[tid] = cnp[0 * 64 + tid] + cnp[1 * 64 + tid] + cnp[2 * 64 + tid] + cnp[3 * 64 + tid];
    else if (tid < 128) {
        const int r = tid - 64;
        zz[r] = znp[0 * 64 + r] + znp[1 * 64 + r] + znp[2 * 64 + r] + znp[3 * 64 + r];
    }
    __syncthreads();

    // ---- main loop: 4 rows x 4 cols per thread, packed f32x2 FMAs ----
    const int tx = tid & 15;     // cluster group: cols 4*tx..4*tx+3
    const int ty = tid >> 4;     // row group:     rows 4*ty..4*ty+3
    const float* cp = cT + 4 * tx;
    const float* zp = zdupT + 8 * ty;

    ull a00 = 0, a01 = 0, a10 = 0, a11 = 0;
    ull a20 = 0, a21 = 0, a30 = 0, a31 = 0;

    #pragma unroll 8
    for (int k = 0; k < H; k++) {
        const ulonglong2 cv  = *(const ulonglong2*)(cp + k * KC);        // {c0,c1},{c2,c3}
        const ulonglong2 z01 = *(const ulonglong2*)(zp + k * (2 * RPB)); // {z0,z0},{z1,z1}
        const ulonglong2 z23 = *(const ulonglong2*)(zp + k * (2 * RPB) + 4);
        FMA2(a00, z01.x, cv.x); FMA2(a01, z01.x, cv.y);
        FMA2(a10, z01.y, cv.x); FMA2(a11, z01.y, cv.y);
        FMA2(a20, z23.x, cv.x); FMA2(a21, z23.x, cv.y);
        FMA2(a30, z23.y, cv.x); FMA2(a31, z23.y, cv.y);
    }

    // unpack accumulators into a[4][4]
    float a[4][4];
    {
        const float2 f00 = *(float2*)&a00, f01 = *(float2*)&a01;
        const float2 f10 = *(float2*)&a10, f11 = *(float2*)&a11;
        const float2 f20 = *(float2*)&a20, f21 = *(float2*)&a21;
        const float2 f30 = *(float2*)&a30, f31 = *(float2*)&a31;
        a[0][0] = f00.x; a[0][1] = f00.y; a[0][2] = f01.x; a[0][3] = f01.y;
        a[1][0] = f10.x; a[1][1] = f10.y; a[1][2] = f11.x; a[1][3] = f11.y;
        a[2][0] = f20.x; a[2][1] = f20.y; a[2][2] = f21.x; a[2][3] = f21.y;
        a[3][0] = f30.x; a[3][1] = f30.y; a[3][2] = f31.x; a[3][3] = f31.y;
    }

    // ---- epilogue: q = 1/(1 + dist), row-normalize ----
    float cn4[4], zz4[4];
    #pragma unroll
    for (int j = 0; j < 4; j++) cn4[j] = cn[4 * tx + j];
    #pragma unroll
    for (int i = 0; i < 4; i++) zz4[i] = zz[4 * ty + i];

    #pragma unroll
    for (int i = 0; i < 4; i++)
        #pragma unroll
        for (int j = 0; j < 4; j++) {
            const float d2 = fmaxf(zz4[i] + cn4[j] - 2.f * a[i][j], 0.f);
            a[i][j] = 1.f / (1.f + sqrtf(d2));
        }

    float rs[4];
    #pragma unroll
    for (int i = 0; i < 4; i++)
        rs[i] = a[i][0] + a[i][1] + a[i][2] + a[i][3];
    #pragma unroll
    for (int m = 1; m < 16; m <<= 1) {
        #pragma unroll
        for (int i = 0; i < 4; i++)
            rs[i] += __shfl_xor_sync(0xffffffffu, rs[i], m);
    }
    #pragma unroll
    for (int i = 0; i < 4; i++) {
        const float inv = 1.f / rs[i];
        a[i][0] *= inv; a[i][1] *= inv; a[i][2] *= inv; a[i][3] *= inv;
    }

    // Q writes (coalesced)
    #pragma unroll
    for (int i = 0; i < 4; i++) {
        const int row = row0 + 4 * ty + i;
        *(float4*)(Qout + (size_t)row * KC + 4 * tx) =
            make_float4(a[i][0], a[i][1], a[i][2], a[i][3]);
    }

    // per-block column partials of normalized Q (deterministic smem tree)
    *(float4*)(colred + ty * KC + 4 * tx) =
        make_float4(a[0][0] + a[1][0] + a[2][0] + a[3][0],
                    a[0][1] + a[1][1] + a[2][1] + a[3][1],
                    a[0][2] + a[1][2] + a[2][2] + a[3][2],
                    a[0][3] + a[1][3] + a[2][3] + a[3][3]);
    __syncthreads();
    if (tid < KC) {
        float s = 0.f;
        #pragma unroll
        for (int t = 0; t < 16; t++) s += colred[t * KC + tid];
        g_colpart[blockIdx.x * KC + tid] = s;
    }

    // ---- last-arriving block reduces column partials -> g_csi ----
    __threadfence();
    __shared__ unsigned int s_last;
    __syncthreads();           // all partial STGs issued before the arrival mark
    if (tid == 0) {
        const unsigned int old = atomicAdd(&g_cnt, 1u);
        s_last = (old == NBLK - 1) ? 1u : 0u;
    }
    __syncthreads();
    if (s_last) {
        // reuse colred region: [4][64] partials
        const int j  = tid & 63;
        const int pr = tid >> 6;
        float s = 0.f;
        #pragma unroll 8
        for (int b = pr; b < NBLK; b += 4) s += __ldcg(&g_colpart[b * KC + j]);
        colred[pr * KC + j] = s;
        __syncthreads();
        if (tid < KC)
            g_csi[tid] = 1.0f / (colred[0 * KC + tid] + colred[1 * KC + tid] +
                                 colred[2 * KC + tid] + colred[3 * KC + tid]);
        if (tid == 0) g_cnt = 0;   // reset for next graph replay
    }
}

// ---------------------------------------------------------------------------
// Kernel 2: P = rownorm( Q^2 * csi ).  32 rows/block, 256 blocks, coalesced.
// ---------------------------------------------------------------------------
__global__ __launch_bounds__(256)
void p_kernel(const float* __restrict__ Qin, float* __restrict__ Pout)
{
    __shared__ float csi_s[KC];
    const int tid = threadIdx.x;
    if (tid < KC) csi_s[tid] = g_csi[tid];
    __syncthreads();

    const int lane = tid & 31, warp = tid >> 5;
    const float w0 = csi_s[2 * lane];
    const float w1 = csi_s[2 * lane + 1];
    const int rowbase = blockIdx.x * 32 + warp * 4;

    #pragma unroll
    for (int rr = 0; rr < 4; rr++) {
        const int row = rowbase + rr;
        const float2 q = *(const float2*)(Qin + (size_t)row * KC + 2 * lane);
        const float p0 = q.x * q.x * w0;
        const float p1 = q.y * q.y * w1;
        float rs = p0 + p1;
        #pragma unroll
        for (int m = 1; m < 32; m <<= 1) rs += __shfl_xor_sync(0xffffffffu, rs, m);
        const float inv = 1.0f / rs;
        float2 o; o.x = p0 * inv; o.y = p1 * inv;
        *(float2*)(Pout + (size_t)row * KC + 2 * lane) = o;
    }
}

// ---------------------------------------------------------------------------
extern "C" void kernel_launch(void* const* d_in, const int* in_sizes, int n_in,
                              void* d_out, int out_size)
{
    const float* z    = (const float*)d_in[0];   // (8192, 256)
    const float* cent = (const float*)d_in[1];   // (64, 256)
    float* Q = (float*)d_out;                    // (8192, 64)
    float* P = Q + (size_t)BS * KC;              // (8192, 64)

    const size_t smem_bytes =
        (size_t)(H * 2 * RPB + H * KC + 4 * KC + 4 * RPB + KC + RPB + 16 * KC) * sizeof(float);

    cudaFuncSetAttribute(qk_kernel, cudaFuncAttributeMaxDynamicSharedMemorySize,
                         (int)smem_bytes);

    qk_kernel<<<NBLK, 256, smem_bytes>>>(z, cent, Q);
    p_kernel<<<BS / 32, 256>>>(Q, P);
}

// round 10
// speedup vs baseline: 1.3034x; 1.3034x over previous
#include <cuda_runtime.h>

#define BS   8192
#define H    256
#define KC   64
#define RPB  64
#define NBLK (BS / RPB)        // 128 blocks, all co-resident (1 CTA/SM)
#define NTHR 512
#define SZ   66                // zT row stride (even -> 8B-aligned float2)

// Per-block column partials of normalized Q; grid-barrier counter (epoch-based,
// never reset -> safe across graph replays, deterministic work every call).
__device__ float g_colpart[NBLK * KC];
__device__ unsigned int g_bar = 0;

// ---------------------------------------------------------------------------
// Single persistent kernel:
//   phase A: stage cT (XOR-swizzled, conflict-free) + zT, fused norms
//   phase B: 64x64 distance tile, 2 rows x 4 cols per thread (16 warps/SM)
//   phase C: Q = rownorm(1/(1+dist)) -> gmem; per-block column partials
//   phase D: grid-wide barrier (all 128 CTAs resident)
//   phase E: redundant per-block colsum reduce -> csi (smem)
//   phase F: P = rownorm(Q^2 * csi) from REGISTER-resident Q -> gmem
// ---------------------------------------------------------------------------
__global__ __launch_bounds__(NTHR, 1)
void cluster_kernel(const float* __restrict__ z, const float* __restrict__ cent,
                    float* __restrict__ Qout, float* __restrict__ Pout)
{
    extern __shared__ float smem[];
    float* cT     = smem;              // [256][64]  swizzled 16B chunks
    float* zT     = cT + H * KC;       // [256][SZ]
    float* cnp    = zT + H * SZ;       // [8][64]  (reused in phase E)
    float* znp    = cnp + 8 * KC;      // [8][64]  (reused in colpart reduce)
    float* cn     = znp + 8 * KC;      // [64]  ||c_j||^2
    float* zz     = cn + KC;           // [64]  ||z_r||^2
    float* colred = zz + RPB;          // [32][64]
    float* csi_s  = colred + 32 * KC;  // [64]

    const int tid  = threadIdx.x;
    const int row0 = blockIdx.x * RPB;

    // ---------------- phase A: staging (coalesced LDG, low-conflict STS) ----
    {
        const int r  = tid >> 3;       // 0..63 (z-row / centroid index)
        const int cg = tid & 7;        // column group

        float zsq = 0.f;
        #pragma unroll
        for (int p = 0; p < 8; p++) {
            const int k0 = cg * 4 + p * 32;
            const float4 v = *(const float4*)(z + (size_t)(row0 + r) * H + k0);
            zT[(k0 + 0) * SZ + r] = v.x;
            zT[(k0 + 1) * SZ + r] = v.y;
            zT[(k0 + 2) * SZ + r] = v.z;
            zT[(k0 + 3) * SZ + r] = v.w;
            zsq = fmaf(v.x, v.x, zsq); zsq = fmaf(v.y, v.y, zsq);
            zsq = fmaf(v.z, v.z, zsq); zsq = fmaf(v.w, v.w, zsq);
        }
        znp[cg * 64 + r] = zsq;

        float csq = 0.f;
        const int jc = r >> 2, jl = r & 3;
        #pragma unroll
        for (int p = 0; p < 8; p++) {
            const int k0 = cg * 4 + p * 32;
            const float4 v = *(const float4*)(cent + (size_t)r * H + k0);
            float vv[4] = {v.x, v.y, v.z, v.w};
            #pragma unroll
            for (int i = 0; i < 4; i++) {
                const int k = k0 + i;
                // c[j][k] stored at chunk (j>>2) ^ ((k>>2)&15): conflict-free
                // staging STS AND conflict-free main-loop LDS.128.
                cT[k * KC + 4 * (jc ^ ((k >> 2) & 15)) + jl] = vv[i];
                csq = fmaf(vv[i], vv[i], csq);
            }
        }
        cnp[cg * 64 + r] = csq;
    }
    __syncthreads();

    if (tid < 64) {
        float s = 0.f;
        #pragma unroll
        for (int g = 0; g < 8; g++) s += cnp[g * 64 + tid];
        cn[tid] = s;
    } else if (tid < 128) {
        const int r = tid - 64;
        float s = 0.f;
        #pragma unroll
        for (int g = 0; g < 8; g++) s += znp[g * 64 + r];
        zz[r] = s;
    }
    __syncthreads();

    // ---------------- phase B: main loop, 2 rows x 4 cols per thread --------
    const int tx = tid & 15;           // cols 4*tx..4*tx+3
    const int ty = tid >> 4;           // rows 2*ty, 2*ty+1   (0..31)
    const float* zrow = zT + 2 * ty;

    float a00 = 0.f, a01 = 0.f, a02 = 0.f, a03 = 0.f;
    float a10 = 0.f, a11 = 0.f, a12 = 0.f, a13 = 0.f;

    #pragma unroll 8
    for (int k = 0; k < H; k++) {
        const float4 cv = *(const float4*)(cT + k * KC + 4 * (tx ^ ((k >> 2) & 15)));
        const float2 zv = *(const float2*)(zrow + k * SZ);
        a00 = fmaf(zv.x, cv.x, a00); a01 = fmaf(zv.x, cv.y, a01);
        a02 = fmaf(zv.x, cv.z, a02); a03 = fmaf(zv.x, cv.w, a03);
        a10 = fmaf(zv.y, cv.x, a10); a11 = fmaf(zv.y, cv.y, a11);
        a12 = fmaf(zv.y, cv.z, a12); a13 = fmaf(zv.y, cv.w, a13);
    }

    // ---------------- phase C: Q epilogue ----------------------------------
    const float cn0 = cn[4 * tx + 0], cn1 = cn[4 * tx + 1];
    const float cn2 = cn[4 * tx + 2], cn3 = cn[4 * tx + 3];
    const float zz0 = zz[2 * ty + 0], zz1 = zz[2 * ty + 1];

    a00 = 1.f / (1.f + sqrtf(fmaxf(zz0 + cn0 - 2.f * a00, 0.f)));
    a01 = 1.f / (1.f + sqrtf(fmaxf(zz0 + cn1 - 2.f * a01, 0.f)));
    a02 = 1.f / (1.f + sqrtf(fmaxf(zz0 + cn2 - 2.f * a02, 0.f)));
    a03 = 1.f / (1.f + sqrtf(fmaxf(zz0 + cn3 - 2.f * a03, 0.f)));
    a10 = 1.f / (1.f + sqrtf(fmaxf(zz1 + cn0 - 2.f * a10, 0.f)));
    a11 = 1.f / (1.f + sqrtf(fmaxf(zz1 + cn1 - 2.f * a11, 0.f)));
    a12 = 1.f / (1.f + sqrtf(fmaxf(zz1 + cn2 - 2.f * a12, 0.f)));
    a13 = 1.f / (1.f + sqrtf(fmaxf(zz1 + cn3 - 2.f * a13, 0.f)));

    float rs0 = a00 + a01 + a02 + a03;
    float rs1 = a10 + a11 + a12 + a13;
    #pragma unroll
    for (int m = 1; m < 16; m <<= 1) {
        rs0 += __shfl_xor_sync(0xffffffffu, rs0, m);
        rs1 += __shfl_xor_sync(0xffffffffu, rs1, m);
    }
    const float i0 = 1.f / rs0;
    const float i1 = 1.f / rs1;
    a00 *= i0; a01 *= i0; a02 *= i0; a03 *= i0;
    a10 *= i1; a11 *= i1; a12 *= i1; a13 *= i1;

    const int r0g = row0 + 2 * ty;
    *(float4*)(Qout + (size_t)r0g * KC + 4 * tx)       = make_float4(a00, a01, a02, a03);
    *(float4*)(Qout + (size_t)(r0g + 1) * KC + 4 * tx) = make_float4(a10, a11, a12, a13);

    // per-block column partials (deterministic smem tree)
    *(float4*)(colred + ty * KC + 4 * tx) =
        make_float4(a00 + a10, a01 + a11, a02 + a12, a03 + a13);
    __syncthreads();
    {
        const int j = tid & 63, g = tid >> 6;      // g: 0..7
        znp[g * 64 + j] = colred[g * KC + j]        + colred[(g + 8)  * KC + j]
                        + colred[(g + 16) * KC + j] + colred[(g + 24) * KC + j];
    }
    __syncthreads();
    if (tid < KC) {
        float s = 0.f;
        #pragma unroll
        for (int g = 0; g < 8; g++) s += znp[g * 64 + tid];
        g_colpart[blockIdx.x * KC + tid] = s;
    }

    // ---------------- phase D: grid-wide barrier (epoch counter) -----------
    __threadfence();
    __syncthreads();
    if (tid == 0) {
        const unsigned int old    = atomicAdd(&g_bar, 1u);
        const unsigned int target = (old / NBLK + 1u) * (unsigned)NBLK;
        unsigned int cur;
        do {
            asm volatile("ld.acquire.gpu.global.u32 %0, [%1];"
                         : "=r"(cur) : "l"(&g_bar) : "memory");
            if (cur < target) __nanosleep(40);
        } while (cur < target);
    }
    __syncthreads();

    // ---------------- phase E: redundant csi reduce (L2 reads) -------------
    {
        const int j = tid & 63, pr = tid >> 6;     // pr: 0..7
        float s = 0.f;
        #pragma unroll 4
        for (int b = pr; b < NBLK; b += 8) s += __ldcg(&g_colpart[b * KC + j]);
        cnp[pr * 64 + j] = s;
    }
    __syncthreads();
    if (tid < KC) {
        float s = 0.f;
        #pragma unroll
        for (int g = 0; g < 8; g++) s += cnp[g * 64 + tid];
        csi_s[tid] = 1.0f / s;
    }
    __syncthreads();

    // ---------------- phase F: P from register-resident Q ------------------
    const float w0 = csi_s[4 * tx + 0], w1 = csi_s[4 * tx + 1];
    const float w2 = csi_s[4 * tx + 2], w3 = csi_s[4 * tx + 3];

    const float p00 = a00 * a00 * w0, p01 = a01 * a01 * w1;
    const float p02 = a02 * a02 * w2, p03 = a03 * a03 * w3;
    const float p10 = a10 * a10 * w0, p11 = a11 * a11 * w1;
    const float p12 = a12 * a12 * w2, p13 = a13 * a13 * w3;

    float ps0 = p00 + p01 + p02 + p03;
    float ps1 = p10 + p11 + p12 + p13;
    #pragma unroll
    for (int m = 1; m < 16; m <<= 1) {
        ps0 += __shfl_xor_sync(0xffffffffu, ps0, m);
        ps1 += __shfl_xor_sync(0xffffffffu, ps1, m);
    }
    const float q0 = 1.f / ps0;
    const float q1 = 1.f / ps1;

    *(float4*)(Pout + (size_t)r0g * KC + 4 * tx) =
        make_float4(p00 * q0, p01 * q0, p02 * q0, p03 * q0);
    *(float4*)(Pout + (size_t)(r0g + 1) * KC + 4 * tx) =
        make_float4(p10 * q1, p11 * q1, p12 * q1, p13 * q1);
}

// ---------------------------------------------------------------------------
extern "C" void kernel_launch(void* const* d_in, const int* in_sizes, int n_in,
                              void* d_out, int out_size)
{
    const float* z    = (const float*)d_in[0];   // (8192, 256)
    const float* cent = (const float*)d_in[1];   // (64, 256)
    float* Q = (float*)d_out;                    // (8192, 64)
    float* P = Q + (size_t)BS * KC;              // (8192, 64)

    const size_t smem_bytes =
        (size_t)(H * KC + H * SZ + 8 * KC + 8 * KC + KC + RPB + 32 * KC + KC)
        * sizeof(float);                          // ~143 KB -> 1 CTA/SM

    cudaFuncSetAttribute(cluster_kernel, cudaFuncAttributeMaxDynamicSharedMemorySize,
                         (int)smem_bytes);

    cluster_kernel<<<NBLK, NTHR, smem_bytes>>>(z, cent, Q, P);
}